// round 1
// baseline (speedup 1.0000x reference)
#include <cuda_runtime.h>
#include <math.h>

// Problem sizes (fixed by the dataset)
#define BATCH 8
#define DDIM  512
#define NPTS  2048
#define MPTS  2048

// Scratch (static __device__ arrays: allowed; no cudaMalloc anywhere)
__device__ float g_scores[(size_t)BATCH * NPTS * MPTS];   // 134 MB
__device__ float g_corr[BATCH * 3 * NPTS];                // src_corr [B,3,N]

// ---------------------------------------------------------------------------
// Kernel 1: scores[b,n,m] = (1/sqrt(D)) * sum_d A[b,d,n] * Bm[b,d,m]
// Tiled fp32 SIMT GEMM. 128x128 block tile, 16 K-chunk, 256 threads, 8x8/thread.
// ---------------------------------------------------------------------------
#define BM 128
#define BN 128
#define BK 16

__global__ __launch_bounds__(256, 2)
void gemm_scores_kernel(const float* __restrict__ A, const float* __restrict__ Bm) {
    const int b  = blockIdx.z;
    const int n0 = blockIdx.y * BM;
    const int m0 = blockIdx.x * BN;

    const float* Ab = A  + (size_t)b * DDIM * NPTS + n0;
    const float* Bb = Bm + (size_t)b * DDIM * MPTS + m0;

    __shared__ float As[BK][BM];
    __shared__ float Bs[BK][BN];

    const int tid = threadIdx.x;
    const int tn  = tid & 15;   // 0..15 (m direction)
    const int tm  = tid >> 4;   // 0..15 (n direction)

    // loader mapping: 16 rows x 128 cols = 512 float4, 256 threads -> 2 rows each
    const int lrow = tid >> 5;          // 0..7
    const int lcol = (tid & 31) * 4;    // 0..124

    float acc[8][8];
#pragma unroll
    for (int i = 0; i < 8; i++)
#pragma unroll
        for (int j = 0; j < 8; j++) acc[i][j] = 0.f;

    for (int k0 = 0; k0 < DDIM; k0 += BK) {
        *(float4*)&As[lrow    ][lcol] = *(const float4*)&Ab[(size_t)(k0 + lrow    ) * NPTS + lcol];
        *(float4*)&As[lrow + 8][lcol] = *(const float4*)&Ab[(size_t)(k0 + lrow + 8) * NPTS + lcol];
        *(float4*)&Bs[lrow    ][lcol] = *(const float4*)&Bb[(size_t)(k0 + lrow    ) * MPTS + lcol];
        *(float4*)&Bs[lrow + 8][lcol] = *(const float4*)&Bb[(size_t)(k0 + lrow + 8) * MPTS + lcol];
        __syncthreads();

#pragma unroll
        for (int kk = 0; kk < BK; kk++) {
            float af[8], bf[8];
            float4 a0 = *(float4*)&As[kk][tm * 8];
            float4 a1 = *(float4*)&As[kk][tm * 8 + 4];
            float4 b0 = *(float4*)&Bs[kk][tn * 8];
            float4 b1 = *(float4*)&Bs[kk][tn * 8 + 4];
            af[0]=a0.x; af[1]=a0.y; af[2]=a0.z; af[3]=a0.w;
            af[4]=a1.x; af[5]=a1.y; af[6]=a1.z; af[7]=a1.w;
            bf[0]=b0.x; bf[1]=b0.y; bf[2]=b0.z; bf[3]=b0.w;
            bf[4]=b1.x; bf[5]=b1.y; bf[6]=b1.z; bf[7]=b1.w;
#pragma unroll
            for (int i = 0; i < 8; i++)
#pragma unroll
                for (int j = 0; j < 8; j++)
                    acc[i][j] += af[i] * bf[j];
        }
        __syncthreads();
    }

    const float scale = 0.044194173824159216f;  // 1/sqrt(512)
    float* out = g_scores + (size_t)b * NPTS * MPTS;
#pragma unroll
    for (int i = 0; i < 8; i++) {
        const size_t row = (size_t)(n0 + tm * 8 + i) * MPTS + m0 + tn * 8;
        float4 w0, w1;
        w0.x = acc[i][0]*scale; w0.y = acc[i][1]*scale; w0.z = acc[i][2]*scale; w0.w = acc[i][3]*scale;
        w1.x = acc[i][4]*scale; w1.y = acc[i][5]*scale; w1.z = acc[i][6]*scale; w1.w = acc[i][7]*scale;
        *(float4*)&out[row]     = w0;
        *(float4*)&out[row + 4] = w1;
    }
}

// ---------------------------------------------------------------------------
// Kernel 2: per (b,n) softmax over m fused with weighted sum of tgt ->
// src_corr[b,:,n]. One block (256 threads) per row.
// ---------------------------------------------------------------------------
__global__ __launch_bounds__(256)
void softmax_corr_kernel(const float* __restrict__ tgt) {
    const int n = blockIdx.x;
    const int b = blockIdx.y;
    const float* row = g_scores + ((size_t)b * NPTS + n) * MPTS;
    const float* tg  = tgt + (size_t)b * 3 * MPTS;
    const int tid = threadIdx.x;

    __shared__ float red[256];

    float v[8];
    float mx = -1e30f;
#pragma unroll
    for (int i = 0; i < 8; i++) {
        v[i] = row[tid + i * 256];
        mx = fmaxf(mx, v[i]);
    }
    // block max
    red[tid] = mx; __syncthreads();
    for (int s = 128; s > 0; s >>= 1) {
        if (tid < s) red[tid] = fmaxf(red[tid], red[tid + s]);
        __syncthreads();
    }
    const float smax = red[0];
    __syncthreads();

    float se = 0.f, cx = 0.f, cy = 0.f, cz = 0.f;
#pragma unroll
    for (int i = 0; i < 8; i++) {
        const int m = tid + i * 256;
        const float e = __expf(v[i] - smax);
        se += e;
        cx += e * tg[m];
        cy += e * tg[MPTS + m];
        cz += e * tg[2 * MPTS + m];
    }

    // 4 block sums
    float vals[4] = {se, cx, cy, cz};
    float outv[4];
#pragma unroll
    for (int r = 0; r < 4; r++) {
        red[tid] = vals[r]; __syncthreads();
        for (int s = 128; s > 0; s >>= 1) {
            if (tid < s) red[tid] += red[tid + s];
            __syncthreads();
        }
        outv[r] = red[0];
        __syncthreads();
    }

    if (tid == 0) {
        const float inv = 1.0f / outv[0];
        float* cp = g_corr + b * 3 * NPTS;
        cp[n]            = outv[1] * inv;
        cp[NPTS + n]     = outv[2] * inv;
        cp[2 * NPTS + n] = outv[3] * inv;
    }
}

// ---------------------------------------------------------------------------
// Kernel 3: per batch — reductions (means, H) then 3x3 Procrustes in double.
// One block per batch.
// Output layout: out[0:72] = R (B,3,3) row-major; out[72:96] = t (B,3).
// ---------------------------------------------------------------------------
__global__ __launch_bounds__(256)
void finalize_kernel(const float* __restrict__ src, const float* __restrict__ tgt,
                     float* __restrict__ out) {
    const int b   = blockIdx.x;
    const int tid = threadIdx.x;

    const float* sp = src + (size_t)b * 3 * NPTS;
    const float* cp = g_corr + (size_t)b * 3 * NPTS;
    const float* tp = tgt + (size_t)b * 3 * MPTS;

    // 18 accumulators: Ssum[3], Csum[3], Tsum[3], P[9]
    __shared__ double acc[18];
    if (tid < 18) acc[tid] = 0.0;
    __syncthreads();

    double Ssum[3] = {0,0,0}, Csum[3] = {0,0,0}, Tsum[3] = {0,0,0}, P[9] = {0,0,0,0,0,0,0,0,0};
    for (int n = tid; n < NPTS; n += 256) {
        double s0 = sp[n], s1 = sp[NPTS + n], s2 = sp[2 * NPTS + n];
        double c0 = cp[n], c1 = cp[NPTS + n], c2 = cp[2 * NPTS + n];
        double t0 = tp[n], t1 = tp[MPTS + n], t2 = tp[2 * MPTS + n];
        Ssum[0] += s0; Ssum[1] += s1; Ssum[2] += s2;
        Csum[0] += c0; Csum[1] += c1; Csum[2] += c2;
        Tsum[0] += t0; Tsum[1] += t1; Tsum[2] += t2;
        P[0] += s0*c0; P[1] += s0*c1; P[2] += s0*c2;
        P[3] += s1*c0; P[4] += s1*c1; P[5] += s1*c2;
        P[6] += s2*c0; P[7] += s2*c1; P[8] += s2*c2;
    }
#pragma unroll
    for (int i = 0; i < 3; i++) {
        atomicAdd(&acc[i],     Ssum[i]);
        atomicAdd(&acc[3 + i], Csum[i]);
        atomicAdd(&acc[6 + i], Tsum[i]);
    }
#pragma unroll
    for (int i = 0; i < 9; i++) atomicAdd(&acc[9 + i], P[i]);
    __syncthreads();

    if (tid != 0) return;

    const double invN = 1.0 / (double)NPTS;
    double sm[3], cm[3], tm_[3];
    for (int i = 0; i < 3; i++) {
        sm[i]  = acc[i] * invN;
        cm[i]  = acc[3 + i] * invN;
        tm_[i] = acc[6 + i] * invN;
    }
    // H[i][j] = P[i][j] - N * sm[i]*cm[j]
    double H[3][3];
    for (int i = 0; i < 3; i++)
        for (int j = 0; j < 3; j++)
            H[i][j] = acc[9 + i * 3 + j] - (double)NPTS * sm[i] * cm[j];

    // A = H^T H (symmetric PSD)
    double A[3][3];
    for (int i = 0; i < 3; i++)
        for (int j = 0; j < 3; j++) {
            double s = 0.0;
            for (int k = 0; k < 3; k++) s += H[k][i] * H[k][j];
            A[i][j] = s;
        }

    // Jacobi eigensolver
    double V[3][3] = {{1,0,0},{0,1,0},{0,0,1}};
    const int pp[3] = {0, 0, 1};
    const int qq[3] = {1, 2, 2};
    for (int it = 0; it < 30; it++) {
        const int p = pp[it % 3], q = qq[it % 3];
        const double apq = A[p][q];
        if (fabs(apq) < 1e-300) continue;
        const double theta = (A[q][q] - A[p][p]) / (2.0 * apq);
        const double t = (theta >= 0 ? 1.0 : -1.0) / (fabs(theta) + sqrt(theta * theta + 1.0));
        const double c = 1.0 / sqrt(t * t + 1.0);
        const double s = t * c;
        for (int k = 0; k < 3; k++) {
            const double akp = A[k][p], akq = A[k][q];
            A[k][p] = c * akp - s * akq;
            A[k][q] = s * akp + c * akq;
        }
        for (int k = 0; k < 3; k++) {
            const double apk = A[p][k], aqk = A[q][k];
            A[p][k] = c * apk - s * aqk;
            A[q][k] = s * apk + c * aqk;
        }
        for (int k = 0; k < 3; k++) {
            const double vkp = V[k][p], vkq = V[k][q];
            V[k][p] = c * vkp - s * vkq;
            V[k][q] = s * vkp + c * vkq;
        }
    }

    // sort eigenvalues descending, keep column indices
    double lam[3] = {A[0][0], A[1][1], A[2][2]};
    int idx[3] = {0, 1, 2};
    for (int i = 0; i < 2; i++)
        for (int j = i + 1; j < 3; j++)
            if (lam[idx[j]] > lam[idx[i]]) { int tmpi = idx[i]; idx[i] = idx[j]; idx[j] = tmpi; }

    double v1[3], v2[3];
    for (int k = 0; k < 3; k++) { v1[k] = V[k][idx[0]]; v2[k] = V[k][idx[1]]; }

    // u1 = normalize(H v1); u2 = normalize(H v2 - (u1.Hv2) u1)
    double hv1[3], hv2[3];
    for (int i = 0; i < 3; i++) {
        hv1[i] = H[i][0]*v1[0] + H[i][1]*v1[1] + H[i][2]*v1[2];
        hv2[i] = H[i][0]*v2[0] + H[i][1]*v2[1] + H[i][2]*v2[2];
    }
    double n1 = sqrt(hv1[0]*hv1[0] + hv1[1]*hv1[1] + hv1[2]*hv1[2]);
    double u1[3] = {hv1[0]/n1, hv1[1]/n1, hv1[2]/n1};
    double d12 = u1[0]*hv2[0] + u1[1]*hv2[1] + u1[2]*hv2[2];
    double w[3] = {hv2[0] - d12*u1[0], hv2[1] - d12*u1[1], hv2[2] - d12*u1[2]};
    double n2 = sqrt(w[0]*w[0] + w[1]*w[1] + w[2]*w[2]);
    double u2[3] = {w[0]/n2, w[1]/n2, w[2]/n2};

    // right-handed completion (== Kabsch det-fix)
    double v3[3] = {v1[1]*v2[2]-v1[2]*v2[1], v1[2]*v2[0]-v1[0]*v2[2], v1[0]*v2[1]-v1[1]*v2[0]};
    double u3[3] = {u1[1]*u2[2]-u1[2]*u2[1], u1[2]*u2[0]-u1[0]*u2[2], u1[0]*u2[1]-u1[1]*u2[0]};

    double R[3][3];
    for (int i = 0; i < 3; i++)
        for (int j = 0; j < 3; j++)
            R[i][j] = v1[i]*u1[j] + v2[i]*u2[j] + v3[i]*u3[j];

    // t = -R @ src_mean + tgt_mean
    double tvec[3];
    for (int i = 0; i < 3; i++)
        tvec[i] = -(R[i][0]*sm[0] + R[i][1]*sm[1] + R[i][2]*sm[2]) + tm_[i];

    for (int i = 0; i < 3; i++)
        for (int j = 0; j < 3; j++)
            out[b * 9 + i * 3 + j] = (float)R[i][j];
    for (int i = 0; i < 3; i++)
        out[BATCH * 9 + b * 3 + i] = (float)tvec[i];
}

// ---------------------------------------------------------------------------
extern "C" void kernel_launch(void* const* d_in, const int* in_sizes, int n_in,
                              void* d_out, int out_size) {
    const float* src_emb = (const float*)d_in[0];
    const float* tgt_emb = (const float*)d_in[1];
    const float* src     = (const float*)d_in[2];
    const float* tgt     = (const float*)d_in[3];
    float* out = (float*)d_out;

    dim3 g1(MPTS / BN, NPTS / BM, BATCH);   // (16,16,8)
    gemm_scores_kernel<<<g1, 256>>>(src_emb, tgt_emb);

    dim3 g2(NPTS, BATCH);
    softmax_corr_kernel<<<g2, 256>>>(tgt);

    finalize_kernel<<<BATCH, 256>>>(src, tgt, out);
}

// round 3
// speedup vs baseline: 1.7443x; 1.7443x over previous
#include <cuda_runtime.h>
#include <cuda_bf16.h>
#include <cstdint>
#include <math.h>

#define BATCH 8
#define DDIM  512
#define NPTS  2048
#define MPTS  2048

// ---------------- scratch (__device__ globals: allowed) ----------------
__device__ float g_scores[(size_t)BATCH * NPTS * MPTS];          // 134 MB
__device__ float g_corr[BATCH * 3 * NPTS];
__device__ __nv_bfloat16 g_Ahi[(size_t)BATCH * NPTS * DDIM];     // [B,N,D] K-major
__device__ __nv_bfloat16 g_Alo[(size_t)BATCH * NPTS * DDIM];
__device__ __nv_bfloat16 g_Bhi[(size_t)BATCH * MPTS * DDIM];     // [B,M,D] K-major
__device__ __nv_bfloat16 g_Blo[(size_t)BATCH * MPTS * DDIM];

// ---------------- helpers ----------------
__device__ __forceinline__ uint32_t smem_u32(const void* p) {
    return (uint32_t)__cvta_generic_to_shared(p);
}
__device__ __forceinline__ void cpa16(uint32_t dst, const void* src) {
    asm volatile("cp.async.cg.shared.global [%0], [%1], 16;"
        :: "r"(dst), "l"(src) : "memory");
}
__device__ __forceinline__ void ldsm4(uint32_t* r, uint32_t addr) {
    asm volatile("ldmatrix.sync.aligned.m8n8.x4.shared.b16 {%0,%1,%2,%3}, [%4];"
        : "=r"(r[0]), "=r"(r[1]), "=r"(r[2]), "=r"(r[3]) : "r"(addr));
}
__device__ __forceinline__ void mma16816(float* c, const uint32_t* a, const uint32_t* b) {
    asm volatile(
        "mma.sync.aligned.m16n8k16.row.col.f32.bf16.bf16.f32 "
        "{%0,%1,%2,%3}, {%4,%5,%6,%7}, {%8,%9}, {%0,%1,%2,%3};"
        : "+f"(c[0]), "+f"(c[1]), "+f"(c[2]), "+f"(c[3])
        : "r"(a[0]), "r"(a[1]), "r"(a[2]), "r"(a[3]), "r"(b[0]), "r"(b[1]));
}

// ---------------------------------------------------------------------------
// Kernel 0: transpose + fp32 -> bf16 hi/lo split.  [B][D][pts] -> [B][pts][D]
// ---------------------------------------------------------------------------
__global__ __launch_bounds__(256)
void convert_transpose_kernel(const float* __restrict__ in,
                              __nv_bfloat16* __restrict__ hi,
                              __nv_bfloat16* __restrict__ lo) {
    __shared__ float tile[32][33];
    const int b  = blockIdx.z;
    const int d0 = blockIdx.y * 32;
    const int n0 = blockIdx.x * 32;
    const int tx = threadIdx.x;        // 0..31
    const int ty = threadIdx.y;        // 0..7

    const float* ip = in + ((size_t)b * DDIM + d0) * NPTS + n0;
#pragma unroll
    for (int r = ty; r < 32; r += 8)
        tile[r][tx] = ip[(size_t)r * NPTS + tx];
    __syncthreads();

    __nv_bfloat16* hp = hi + ((size_t)b * NPTS + n0) * DDIM + d0;
    __nv_bfloat16* lp = lo + ((size_t)b * NPTS + n0) * DDIM + d0;
#pragma unroll
    for (int rr = ty; rr < 32; rr += 8) {
        const float v = tile[tx][rr];               // = in[d0+tx][n0+rr]
        const __nv_bfloat16 h = __float2bfloat16(v);
        const float hv = __bfloat162float(h);
        const __nv_bfloat16 l = __float2bfloat16(v - hv);
        hp[(size_t)rr * DDIM + tx] = h;
        lp[(size_t)rr * DDIM + tx] = l;
    }
}

// ---------------------------------------------------------------------------
// Kernel 1: HMMA (mma.sync bf16) GEMM, split-3.
// Block tile 256(n) x 128(m), K-chunk 32, 512 threads / 16 warps,
// warp tile 32x64, 3-stage cp.async pipeline, swizzled SMEM + ldmatrix.
// ---------------------------------------------------------------------------
#define BM 256
#define BN 128
#define BK 32
#define NCHUNK (DDIM / BK)       // 16

#define STAGE_BYTES 49152
#define OFF_AHI 0
#define OFF_ALO 16384
#define OFF_BHI 32768
#define OFF_BLO 40960
#define GEMM_SMEM (3 * STAGE_BYTES)   // 147456

__global__ __launch_bounds__(512, 1)
void gemm_hmma_kernel() {
    extern __shared__ char smem[];
    const uint32_t sb = smem_u32(smem);
    const int tid  = threadIdx.x;
    const int lane = tid & 31;
    const int wid  = tid >> 5;
    const int b  = blockIdx.z;
    const int n0 = blockIdx.y * BM;
    const int m0 = blockIdx.x * BN;
    const int warpN = wid & 7;     // 8 warps along n (8*32 = 256)
    const int warpM = wid >> 3;    // 2 warps along m (2*64 = 128)

    const __nv_bfloat16* Ah = g_Ahi + ((size_t)b * NPTS + n0) * DDIM;
    const __nv_bfloat16* Al = g_Alo + ((size_t)b * NPTS + n0) * DDIM;
    const __nv_bfloat16* Bh = g_Bhi + ((size_t)b * MPTS + m0) * DDIM;
    const __nv_bfloat16* Bl = g_Blo + ((size_t)b * MPTS + m0) * DDIM;

    // ---- loader mapping (per chunk: A 1024 segs x2 planes, B 512 segs x2) ----
    const int ar0 = tid >> 2,        as0 = tid & 3;          // A idx = tid
    const int ar1 = (tid + 512) >> 2, as1 = (tid + 512) & 3; // A idx = tid+512
    const int br  = tid >> 2,        bs  = tid & 3;          // B idx = tid
    const uint32_t ad0 = (uint32_t)(ar0 * 64 + ((as0 ^ ((ar0 >> 1) & 3)) * 16));
    const uint32_t ad1 = (uint32_t)(ar1 * 64 + ((as1 ^ ((ar1 >> 1) & 3)) * 16));
    const uint32_t bd  = (uint32_t)(br  * 64 + ((bs  ^ ((br  >> 1) & 3)) * 16));

    // ---- compute-side ldmatrix lane addressing ----
    const int rowA = warpN * 32 + (lane & 15);
    const int khA  = lane >> 4;
    const int swzA = (rowA >> 1) & 3;
    const uint32_t abase = (uint32_t)(rowA * 64);
    const int rowB = warpM * 64 + (lane & 7) + ((lane >> 4) << 3);
    const int khB  = (lane >> 3) & 1;
    const int swzB = (rowB >> 1) & 3;
    const uint32_t bbase = (uint32_t)(rowB * 64);

    float acc[2][8][4];
#pragma unroll
    for (int i = 0; i < 2; i++)
#pragma unroll
        for (int j = 0; j < 8; j++)
#pragma unroll
            for (int k = 0; k < 4; k++) acc[i][j][k] = 0.f;

    // preload stages 0, 1
#pragma unroll 1
    for (int pc = 0; pc < 2; pc++) {
        const uint32_t st = sb + pc * STAGE_BYTES;
        const int kofs = pc * BK;
        cpa16(st + OFF_AHI + ad0, Ah + (size_t)ar0 * DDIM + kofs + as0 * 8);
        cpa16(st + OFF_ALO + ad0, Al + (size_t)ar0 * DDIM + kofs + as0 * 8);
        cpa16(st + OFF_AHI + ad1, Ah + (size_t)ar1 * DDIM + kofs + as1 * 8);
        cpa16(st + OFF_ALO + ad1, Al + (size_t)ar1 * DDIM + kofs + as1 * 8);
        cpa16(st + OFF_BHI + bd,  Bh + (size_t)br * DDIM + kofs + bs * 8);
        cpa16(st + OFF_BLO + bd,  Bl + (size_t)br * DDIM + kofs + bs * 8);
        asm volatile("cp.async.commit_group;" ::: "memory");
    }

#pragma unroll 1
    for (int kc = 0; kc < NCHUNK; kc++) {
        asm volatile("cp.async.wait_group 1;" ::: "memory");
        __syncthreads();
        const uint32_t st = sb + (kc % 3) * STAGE_BYTES;

#pragma unroll
        for (int kk = 0; kk < 2; kk++) {
            uint32_t ah[2][4], al[2][4];
            const uint32_t sa = (uint32_t)(((kk * 2 + khA) ^ swzA) * 16);
            ldsm4(ah[0], st + OFF_AHI + abase + sa);
            ldsm4(ah[1], st + OFF_AHI + abase + 1024 + sa);
            ldsm4(al[0], st + OFF_ALO + abase + sa);
            ldsm4(al[1], st + OFF_ALO + abase + 1024 + sa);
            const uint32_t sg = (uint32_t)(((kk * 2 + khB) ^ swzB) * 16);
#pragma unroll
            for (int q = 0; q < 4; q++) {
                uint32_t bh[4], bl[4];
                ldsm4(bh, st + OFF_BHI + bbase + q * 1024 + sg);
                ldsm4(bl, st + OFF_BLO + bbase + q * 1024 + sg);
#pragma unroll
                for (int h = 0; h < 2; h++) {
                    const int j = q * 2 + h;
#pragma unroll
                    for (int i = 0; i < 2; i++) {
                        mma16816(acc[i][j], ah[i], bh + h * 2);
                        mma16816(acc[i][j], ah[i], bl + h * 2);
                        mma16816(acc[i][j], al[i], bh + h * 2);
                    }
                }
            }
        }
        __syncthreads();

        const int nk = kc + 2;
        if (nk < NCHUNK) {
            const uint32_t st2 = sb + (nk % 3) * STAGE_BYTES;
            const int kofs = nk * BK;
            cpa16(st2 + OFF_AHI + ad0, Ah + (size_t)ar0 * DDIM + kofs + as0 * 8);
            cpa16(st2 + OFF_ALO + ad0, Al + (size_t)ar0 * DDIM + kofs + as0 * 8);
            cpa16(st2 + OFF_AHI + ad1, Ah + (size_t)ar1 * DDIM + kofs + as1 * 8);
            cpa16(st2 + OFF_ALO + ad1, Al + (size_t)ar1 * DDIM + kofs + as1 * 8);
            cpa16(st2 + OFF_BHI + bd,  Bh + (size_t)br * DDIM + kofs + bs * 8);
            cpa16(st2 + OFF_BLO + bd,  Bl + (size_t)br * DDIM + kofs + bs * 8);
        }
        asm volatile("cp.async.commit_group;" ::: "memory");
    }

    // ---- epilogue: scale + store ----
    const float scale = 0.044194173824159216f;   // 1/sqrt(512)
    const int gr  = lane >> 2;
    const int tig = lane & 3;
    float* outb = g_scores + (size_t)b * NPTS * MPTS;
#pragma unroll
    for (int i = 0; i < 2; i++) {
        const int r0 = n0 + warpN * 32 + i * 16 + gr;
#pragma unroll
        for (int j = 0; j < 8; j++) {
            const int col = m0 + warpM * 64 + j * 8 + tig * 2;
            float2 v0, v1;
            v0.x = acc[i][j][0] * scale; v0.y = acc[i][j][1] * scale;
            v1.x = acc[i][j][2] * scale; v1.y = acc[i][j][3] * scale;
            *(float2*)&outb[(size_t)r0 * MPTS + col]       = v0;
            *(float2*)&outb[(size_t)(r0 + 8) * MPTS + col] = v1;
        }
    }
}

// ---------------------------------------------------------------------------
// Kernel 2: warp-per-row softmax over m fused with weighted sum of tgt.
// ---------------------------------------------------------------------------
__global__ __launch_bounds__(256)
void softmax_corr_kernel(const float* __restrict__ tgt) {
    const int w = threadIdx.x >> 5, lane = threadIdx.x & 31;
    const int n = blockIdx.x * 8 + w;
    const int b = blockIdx.y;
    const float4* row = (const float4*)(g_scores + ((size_t)b * NPTS + n) * MPTS);
    const float* tg = tgt + (size_t)b * 3 * MPTS;

    float4 v[16];
    float mx = -1e30f;
#pragma unroll
    for (int i = 0; i < 16; i++) {
        v[i] = row[lane + i * 32];
        mx = fmaxf(mx, fmaxf(fmaxf(v[i].x, v[i].y), fmaxf(v[i].z, v[i].w)));
    }
#pragma unroll
    for (int o = 16; o; o >>= 1) mx = fmaxf(mx, __shfl_xor_sync(0xFFFFFFFFu, mx, o));

    float se = 0.f, cx = 0.f, cy = 0.f, cz = 0.f;
#pragma unroll
    for (int i = 0; i < 16; i++) {
        const int q = lane + i * 32;
        const float4 tx = ((const float4*)tg)[q];
        const float4 ty = ((const float4*)(tg + MPTS))[q];
        const float4 tz = ((const float4*)(tg + 2 * MPTS))[q];
        float e;
        e = __expf(v[i].x - mx); se += e; cx += e * tx.x; cy += e * ty.x; cz += e * tz.x;
        e = __expf(v[i].y - mx); se += e; cx += e * tx.y; cy += e * ty.y; cz += e * tz.y;
        e = __expf(v[i].z - mx); se += e; cx += e * tx.z; cy += e * ty.z; cz += e * tz.z;
        e = __expf(v[i].w - mx); se += e; cx += e * tx.w; cy += e * ty.w; cz += e * tz.w;
    }
#pragma unroll
    for (int o = 16; o; o >>= 1) {
        se += __shfl_xor_sync(0xFFFFFFFFu, se, o);
        cx += __shfl_xor_sync(0xFFFFFFFFu, cx, o);
        cy += __shfl_xor_sync(0xFFFFFFFFu, cy, o);
        cz += __shfl_xor_sync(0xFFFFFFFFu, cz, o);
    }
    if (lane == 0) {
        const float inv = 1.0f / se;
        float* cp = g_corr + b * 3 * NPTS;
        cp[n]            = cx * inv;
        cp[NPTS + n]     = cy * inv;
        cp[2 * NPTS + n] = cz * inv;
    }
}

// ---------------------------------------------------------------------------
// Kernel 3: per batch reductions + 3x3 Procrustes in double.
// ---------------------------------------------------------------------------
__global__ __launch_bounds__(256)
void finalize_kernel(const float* __restrict__ src, const float* __restrict__ tgt,
                     float* __restrict__ out) {
    const int b   = blockIdx.x;
    const int tid = threadIdx.x;

    const float* sp = src + (size_t)b * 3 * NPTS;
    const float* cp = g_corr + (size_t)b * 3 * NPTS;
    const float* tp = tgt + (size_t)b * 3 * MPTS;

    __shared__ double acc[18];
    if (tid < 18) acc[tid] = 0.0;
    __syncthreads();

    double Ssum[3] = {0,0,0}, Csum[3] = {0,0,0}, Tsum[3] = {0,0,0}, P[9] = {0,0,0,0,0,0,0,0,0};
    for (int n = tid; n < NPTS; n += 256) {
        double s0 = sp[n], s1 = sp[NPTS + n], s2 = sp[2 * NPTS + n];
        double c0 = cp[n], c1 = cp[NPTS + n], c2 = cp[2 * NPTS + n];
        double t0 = tp[n], t1 = tp[MPTS + n], t2 = tp[2 * MPTS + n];
        Ssum[0] += s0; Ssum[1] += s1; Ssum[2] += s2;
        Csum[0] += c0; Csum[1] += c1; Csum[2] += c2;
        Tsum[0] += t0; Tsum[1] += t1; Tsum[2] += t2;
        P[0] += s0*c0; P[1] += s0*c1; P[2] += s0*c2;
        P[3] += s1*c0; P[4] += s1*c1; P[5] += s1*c2;
        P[6] += s2*c0; P[7] += s2*c1; P[8] += s2*c2;
    }
#pragma unroll
    for (int i = 0; i < 3; i++) {
        atomicAdd(&acc[i],     Ssum[i]);
        atomicAdd(&acc[3 + i], Csum[i]);
        atomicAdd(&acc[6 + i], Tsum[i]);
    }
#pragma unroll
    for (int i = 0; i < 9; i++) atomicAdd(&acc[9 + i], P[i]);
    __syncthreads();

    if (tid != 0) return;

    const double invN = 1.0 / (double)NPTS;
    double sm[3], cm[3], tm_[3];
    for (int i = 0; i < 3; i++) {
        sm[i]  = acc[i] * invN;
        cm[i]  = acc[3 + i] * invN;
        tm_[i] = acc[6 + i] * invN;
    }
    double H[3][3];
    for (int i = 0; i < 3; i++)
        for (int j = 0; j < 3; j++)
            H[i][j] = acc[9 + i * 3 + j] - (double)NPTS * sm[i] * cm[j];

    double A[3][3];
    for (int i = 0; i < 3; i++)
        for (int j = 0; j < 3; j++) {
            double s = 0.0;
            for (int k = 0; k < 3; k++) s += H[k][i] * H[k][j];
            A[i][j] = s;
        }

    double V[3][3] = {{1,0,0},{0,1,0},{0,0,1}};
    const int pp[3] = {0, 0, 1};
    const int qq[3] = {1, 2, 2};
    for (int it = 0; it < 30; it++) {
        const int p = pp[it % 3], q = qq[it % 3];
        const double apq = A[p][q];
        if (fabs(apq) < 1e-300) continue;
        const double theta = (A[q][q] - A[p][p]) / (2.0 * apq);
        const double t = (theta >= 0 ? 1.0 : -1.0) / (fabs(theta) + sqrt(theta * theta + 1.0));
        const double c = 1.0 / sqrt(t * t + 1.0);
        const double s = t * c;
        for (int k = 0; k < 3; k++) {
            const double akp = A[k][p], akq = A[k][q];
            A[k][p] = c * akp - s * akq;
            A[k][q] = s * akp + c * akq;
        }
        for (int k = 0; k < 3; k++) {
            const double apk = A[p][k], aqk = A[q][k];
            A[p][k] = c * apk - s * aqk;
            A[q][k] = s * apk + c * aqk;
        }
        for (int k = 0; k < 3; k++) {
            const double vkp = V[k][p], vkq = V[k][q];
            V[k][p] = c * vkp - s * vkq;
            V[k][q] = s * vkp + c * vkq;
        }
    }

    double lam[3] = {A[0][0], A[1][1], A[2][2]};
    int idx[3] = {0, 1, 2};
    for (int i = 0; i < 2; i++)
        for (int j = i + 1; j < 3; j++)
            if (lam[idx[j]] > lam[idx[i]]) { int tmpi = idx[i]; idx[i] = idx[j]; idx[j] = tmpi; }

    double v1[3], v2[3];
    for (int k = 0; k < 3; k++) { v1[k] = V[k][idx[0]]; v2[k] = V[k][idx[1]]; }

    double hv1[3], hv2[3];
    for (int i = 0; i < 3; i++) {
        hv1[i] = H[i][0]*v1[0] + H[i][1]*v1[1] + H[i][2]*v1[2];
        hv2[i] = H[i][0]*v2[0] + H[i][1]*v2[1] + H[i][2]*v2[2];
    }
    double n1 = sqrt(hv1[0]*hv1[0] + hv1[1]*hv1[1] + hv1[2]*hv1[2]);
    double u1[3] = {hv1[0]/n1, hv1[1]/n1, hv1[2]/n1};
    double d12 = u1[0]*hv2[0] + u1[1]*hv2[1] + u1[2]*hv2[2];
    double w[3] = {hv2[0] - d12*u1[0], hv2[1] - d12*u1[1], hv2[2] - d12*u1[2]};
    double n2 = sqrt(w[0]*w[0] + w[1]*w[1] + w[2]*w[2]);
    double u2[3] = {w[0]/n2, w[1]/n2, w[2]/n2};

    double v3[3] = {v1[1]*v2[2]-v1[2]*v2[1], v1[2]*v2[0]-v1[0]*v2[2], v1[0]*v2[1]-v1[1]*v2[0]};
    double u3[3] = {u1[1]*u2[2]-u1[2]*u2[1], u1[2]*u2[0]-u1[0]*u2[2], u1[0]*u2[1]-u1[1]*u2[0]};

    double R[3][3];
    for (int i = 0; i < 3; i++)
        for (int j = 0; j < 3; j++)
            R[i][j] = v1[i]*u1[j] + v2[i]*u2[j] + v3[i]*u3[j];

    double tvec[3];
    for (int i = 0; i < 3; i++)
        tvec[i] = -(R[i][0]*sm[0] + R[i][1]*sm[1] + R[i][2]*sm[2]) + tm_[i];

    for (int i = 0; i < 3; i++)
        for (int j = 0; j < 3; j++)
            out[b * 9 + i * 3 + j] = (float)R[i][j];
    for (int i = 0; i < 3; i++)
        out[BATCH * 9 + b * 3 + i] = (float)tvec[i];
}

// ---------------------------------------------------------------------------
extern "C" void kernel_launch(void* const* d_in, const int* in_sizes, int n_in,
                              void* d_out, int out_size) {
    const float* src_emb = (const float*)d_in[0];
    const float* tgt_emb = (const float*)d_in[1];
    const float* src     = (const float*)d_in[2];
    const float* tgt     = (const float*)d_in[3];
    float* out = (float*)d_out;

    cudaFuncSetAttribute(gemm_hmma_kernel,
                         cudaFuncAttributeMaxDynamicSharedMemorySize, GEMM_SMEM);

    __nv_bfloat16 *ahi, *alo, *bhi, *blo;
    cudaGetSymbolAddress((void**)&ahi, g_Ahi);
    cudaGetSymbolAddress((void**)&alo, g_Alo);
    cudaGetSymbolAddress((void**)&bhi, g_Bhi);
    cudaGetSymbolAddress((void**)&blo, g_Blo);

    dim3 gc(NPTS / 32, DDIM / 32, BATCH);
    dim3 bc(32, 8);
    convert_transpose_kernel<<<gc, bc>>>(src_emb, ahi, alo);
    convert_transpose_kernel<<<gc, bc>>>(tgt_emb, bhi, blo);

    dim3 g1(MPTS / BN, NPTS / BM, BATCH);   // (16, 8, 8)
    gemm_hmma_kernel<<<g1, 512, GEMM_SMEM>>>();

    dim3 g2(NPTS / 8, BATCH);
    softmax_corr_kernel<<<g2, 256>>>(tgt);

    finalize_kernel<<<BATCH, 256>>>(src, tgt, out);
}

// round 4
// speedup vs baseline: 2.2716x; 1.3022x over previous
#include <cuda_runtime.h>
#include <cuda_fp16.h>
#include <cstdint>
#include <math.h>

#define BATCH 8
#define DDIM  512
#define NPTS  2048
#define MPTS  2048

// ---------------- scratch (__device__ globals: allowed) ----------------
__device__ float g_part[(size_t)BATCH * NPTS * 4];            // se, cx, cy, cz per (b,n)
__device__ __half g_Ahi[(size_t)BATCH * NPTS * DDIM];         // [B,N,D] K-major
__device__ __half g_Bhi[(size_t)BATCH * MPTS * DDIM];         // [B,M,D] K-major
__device__ __half g_Blo[(size_t)BATCH * MPTS * DDIM];

// ---------------- helpers ----------------
__device__ __forceinline__ uint32_t smem_u32(const void* p) {
    return (uint32_t)__cvta_generic_to_shared(p);
}
__device__ __forceinline__ void cpa16(uint32_t dst, const void* src) {
    asm volatile("cp.async.cg.shared.global [%0], [%1], 16;"
        :: "r"(dst), "l"(src) : "memory");
}
__device__ __forceinline__ void ldsm4(uint32_t* r, uint32_t addr) {
    asm volatile("ldmatrix.sync.aligned.m8n8.x4.shared.b16 {%0,%1,%2,%3}, [%4];"
        : "=r"(r[0]), "=r"(r[1]), "=r"(r[2]), "=r"(r[3]) : "r"(addr));
}
__device__ __forceinline__ void mma16816(float* c, const uint32_t* a, const uint32_t* b) {
    asm volatile(
        "mma.sync.aligned.m16n8k16.row.col.f32.f16.f16.f32 "
        "{%0,%1,%2,%3}, {%4,%5,%6,%7}, {%8,%9}, {%0,%1,%2,%3};"
        : "+f"(c[0]), "+f"(c[1]), "+f"(c[2]), "+f"(c[3])
        : "r"(a[0]), "r"(a[1]), "r"(a[2]), "r"(a[3]), "r"(b[0]), "r"(b[1]));
}

// ---------------------------------------------------------------------------
// Kernel 0a: transpose + fp32 -> fp16 (hi only).  [B][D][pts] -> [B][pts][D]
// ---------------------------------------------------------------------------
__global__ __launch_bounds__(256)
void convA_kernel(const float* __restrict__ in, __half* __restrict__ hi) {
    __shared__ float tile[32][33];
    const int b  = blockIdx.z;
    const int d0 = blockIdx.y * 32;
    const int n0 = blockIdx.x * 32;
    const int tx = threadIdx.x;
    const int ty = threadIdx.y;

    const float* ip = in + ((size_t)b * DDIM + d0) * NPTS + n0;
#pragma unroll
    for (int r = ty; r < 32; r += 8)
        tile[r][tx] = ip[(size_t)r * NPTS + tx];
    __syncthreads();

    __half* hp = hi + ((size_t)b * NPTS + n0) * DDIM + d0;
#pragma unroll
    for (int rr = ty; rr < 32; rr += 8)
        hp[(size_t)rr * DDIM + tx] = __float2half(tile[tx][rr]);
}

// ---------------------------------------------------------------------------
// Kernel 0b: transpose + fp32 -> fp16 hi/lo split.
// ---------------------------------------------------------------------------
__global__ __launch_bounds__(256)
void convB_kernel(const float* __restrict__ in,
                  __half* __restrict__ hi, __half* __restrict__ lo) {
    __shared__ float tile[32][33];
    const int b  = blockIdx.z;
    const int d0 = blockIdx.y * 32;
    const int n0 = blockIdx.x * 32;
    const int tx = threadIdx.x;
    const int ty = threadIdx.y;

    const float* ip = in + ((size_t)b * DDIM + d0) * NPTS + n0;
#pragma unroll
    for (int r = ty; r < 32; r += 8)
        tile[r][tx] = ip[(size_t)r * NPTS + tx];
    __syncthreads();

    __half* hp = hi + ((size_t)b * NPTS + n0) * DDIM + d0;
    __half* lp = lo + ((size_t)b * NPTS + n0) * DDIM + d0;
#pragma unroll
    for (int rr = ty; rr < 32; rr += 8) {
        const float v = tile[tx][rr];
        const __half h = __float2half(v);
        const __half l = __float2half(v - __half2float(h));
        hp[(size_t)rr * DDIM + tx] = h;
        lp[(size_t)rr * DDIM + tx] = l;
    }
}

// ---------------------------------------------------------------------------
// Kernel Z: zero the partial accumulators.
// ---------------------------------------------------------------------------
__global__ __launch_bounds__(256)
void zero_part_kernel() {
    const int i = blockIdx.x * 256 + threadIdx.x;
    ((float4*)g_part)[i] = make_float4(0.f, 0.f, 0.f, 0.f);
}

// ---------------------------------------------------------------------------
// Kernel 1: fused GEMM (fp16 2-term HMMA) + exp + weighted partial reduction.
// Block tile 256(n) x 128(m), K-chunk 32, 512 threads / 16 warps,
// warp tile 32x64, 4-stage cp.async pipeline, swizzled SMEM + ldmatrix.
// Epilogue: e = exp(score/sqrt(D)); atomicAdd per-row {sum e, sum e*tgt_xyz}.
// ---------------------------------------------------------------------------
#define BM 256
#define BN 128
#define BK 32
#define NCHUNK (DDIM / BK)       // 16

#define STAGE_BYTES 32768
#define OFF_AHI 0                 // 16384 bytes
#define OFF_BHI 16384             //  8192
#define OFF_BLO 24576             //  8192
#define SM_TGT  (4 * STAGE_BYTES) // 3 * 128 floats = 1536 B
#define GEMM_SMEM (SM_TGT + 1536)

__global__ __launch_bounds__(512, 1)
void gemm_fused_kernel(const float* __restrict__ tgt) {
    extern __shared__ char smem[];
    const uint32_t sb = smem_u32(smem);
    float* smem_tgt = (float*)(smem + SM_TGT);
    const int tid  = threadIdx.x;
    const int lane = tid & 31;
    const int wid  = tid >> 5;
    const int b  = blockIdx.z;
    const int n0 = blockIdx.y * BM;
    const int m0 = blockIdx.x * BN;
    const int warpN = wid & 7;     // 8 warps along n
    const int warpM = wid >> 3;    // 2 warps along m

    // stage the 128-col tgt tile (3 dims) into smem
    if (tid < 384) {
        const int dim = tid >> 7, col = tid & 127;
        smem_tgt[dim * 128 + col] = tgt[(size_t)b * 3 * MPTS + dim * MPTS + m0 + col];
    }

    const __half* Ah = g_Ahi + ((size_t)b * NPTS + n0) * DDIM;
    const __half* Bh = g_Bhi + ((size_t)b * MPTS + m0) * DDIM;
    const __half* Bl = g_Blo + ((size_t)b * MPTS + m0) * DDIM;

    // loader mapping: A 1024 segs (2/thread), B planes 512 segs (1/thread each)
    const int ar0 = tid >> 2,         as0 = tid & 3;
    const int ar1 = (tid + 512) >> 2, as1 = (tid + 512) & 3;
    const int br  = tid >> 2,         bs  = tid & 3;
    const uint32_t ad0 = (uint32_t)(ar0 * 64 + ((as0 ^ ((ar0 >> 1) & 3)) * 16));
    const uint32_t ad1 = (uint32_t)(ar1 * 64 + ((as1 ^ ((ar1 >> 1) & 3)) * 16));
    const uint32_t bd  = (uint32_t)(br  * 64 + ((bs  ^ ((br  >> 1) & 3)) * 16));

    // compute-side ldmatrix addressing
    const int rowA = warpN * 32 + (lane & 15);
    const int khA  = lane >> 4;
    const int swzA = (rowA >> 1) & 3;
    const uint32_t abase = (uint32_t)(rowA * 64);
    const int rowB = warpM * 64 + (lane & 7) + ((lane >> 4) << 3);
    const int khB  = (lane >> 3) & 1;
    const int swzB = (rowB >> 1) & 3;
    const uint32_t bbase = (uint32_t)(rowB * 64);

    float acc[2][8][4];
#pragma unroll
    for (int i = 0; i < 2; i++)
#pragma unroll
        for (int j = 0; j < 8; j++)
#pragma unroll
            for (int k = 0; k < 4; k++) acc[i][j][k] = 0.f;

    // preload 3 stages
#pragma unroll 1
    for (int pc = 0; pc < 3; pc++) {
        const uint32_t st = sb + pc * STAGE_BYTES;
        const int kofs = pc * BK;
        cpa16(st + OFF_AHI + ad0, Ah + (size_t)ar0 * DDIM + kofs + as0 * 8);
        cpa16(st + OFF_AHI + ad1, Ah + (size_t)ar1 * DDIM + kofs + as1 * 8);
        cpa16(st + OFF_BHI + bd,  Bh + (size_t)br * DDIM + kofs + bs * 8);
        cpa16(st + OFF_BLO + bd,  Bl + (size_t)br * DDIM + kofs + bs * 8);
        asm volatile("cp.async.commit_group;" ::: "memory");
    }

#pragma unroll 1
    for (int kc = 0; kc < NCHUNK; kc++) {
        asm volatile("cp.async.wait_group 2;" ::: "memory");
        __syncthreads();
        const uint32_t st = sb + (kc & 3) * STAGE_BYTES;

#pragma unroll
        for (int kk = 0; kk < 2; kk++) {
            uint32_t ah[2][4];
            const uint32_t sa = (uint32_t)(((kk * 2 + khA) ^ swzA) * 16);
            ldsm4(ah[0], st + OFF_AHI + abase + sa);
            ldsm4(ah[1], st + OFF_AHI + abase + 1024 + sa);
            const uint32_t sg = (uint32_t)(((kk * 2 + khB) ^ swzB) * 16);
#pragma unroll
            for (int q = 0; q < 4; q++) {
                uint32_t bh[4], bl[4];
                ldsm4(bh, st + OFF_BHI + bbase + q * 1024 + sg);
                ldsm4(bl, st + OFF_BLO + bbase + q * 1024 + sg);
#pragma unroll
                for (int h = 0; h < 2; h++) {
                    const int j = q * 2 + h;
#pragma unroll
                    for (int i = 0; i < 2; i++) {
                        mma16816(acc[i][j], ah[i], bh + h * 2);
                        mma16816(acc[i][j], ah[i], bl + h * 2);
                    }
                }
            }
        }
        __syncthreads();

        const int nk = kc + 3;
        if (nk < NCHUNK) {
            const uint32_t st2 = sb + (nk & 3) * STAGE_BYTES;
            const int kofs = nk * BK;
            cpa16(st2 + OFF_AHI + ad0, Ah + (size_t)ar0 * DDIM + kofs + as0 * 8);
            cpa16(st2 + OFF_AHI + ad1, Ah + (size_t)ar1 * DDIM + kofs + as1 * 8);
            cpa16(st2 + OFF_BHI + bd,  Bh + (size_t)br * DDIM + kofs + bs * 8);
            cpa16(st2 + OFF_BLO + bd,  Bl + (size_t)br * DDIM + kofs + bs * 8);
        }
        asm volatile("cp.async.commit_group;" ::: "memory");
    }

    // ---- fused epilogue: exp + weighted per-row partial reduction ----
    const float scale = 0.044194173824159216f;   // 1/sqrt(512)
    const int gr  = lane >> 2;
    const int tig = lane & 3;

#pragma unroll
    for (int i = 0; i < 2; i++) {
#pragma unroll
        for (int half = 0; half < 2; half++) {
            float se = 0.f, cx = 0.f, cy = 0.f, cz = 0.f;
#pragma unroll
            for (int j = 0; j < 8; j++) {
#pragma unroll
                for (int cc = 0; cc < 2; cc++) {
                    const float e = __expf(acc[i][j][half * 2 + cc] * scale);
                    const int col = warpM * 64 + j * 8 + tig * 2 + cc;
                    se += e;
                    cx += e * smem_tgt[col];
                    cy += e * smem_tgt[128 + col];
                    cz += e * smem_tgt[256 + col];
                }
            }
            // quad reduce (lanes tig 0..3 share a row)
#pragma unroll
            for (int o = 1; o <= 2; o <<= 1) {
                se += __shfl_xor_sync(0xFFFFFFFFu, se, o);
                cx += __shfl_xor_sync(0xFFFFFFFFu, cx, o);
                cy += __shfl_xor_sync(0xFFFFFFFFu, cy, o);
                cz += __shfl_xor_sync(0xFFFFFFFFu, cz, o);
            }
            if (tig == 0) {
                const int n = n0 + warpN * 32 + i * 16 + half * 8 + gr;
                float* gp = g_part + ((size_t)b * NPTS + n) * 4;
                atomicAdd(gp + 0, se);
                atomicAdd(gp + 1, cx);
                atomicAdd(gp + 2, cy);
                atomicAdd(gp + 3, cz);
            }
        }
    }
}

// ---------------------------------------------------------------------------
// Kernel 3: per batch reductions + 3x3 Procrustes in double.
// Reads corr directly from g_part (cx/se etc.).
// ---------------------------------------------------------------------------
__global__ __launch_bounds__(256)
void finalize_kernel(const float* __restrict__ src, const float* __restrict__ tgt,
                     float* __restrict__ out) {
    const int b   = blockIdx.x;
    const int tid = threadIdx.x;

    const float* sp = src + (size_t)b * 3 * NPTS;
    const float4* pp4 = (const float4*)(g_part + (size_t)b * NPTS * 4);
    const float* tp = tgt + (size_t)b * 3 * MPTS;

    __shared__ double acc[18];
    if (tid < 18) acc[tid] = 0.0;
    __syncthreads();

    double Ssum[3] = {0,0,0}, Csum[3] = {0,0,0}, Tsum[3] = {0,0,0}, P[9] = {0,0,0,0,0,0,0,0,0};
    for (int n = tid; n < NPTS; n += 256) {
        double s0 = sp[n], s1 = sp[NPTS + n], s2 = sp[2 * NPTS + n];
        const float4 pr = pp4[n];
        const double inv = 1.0 / (double)pr.x;
        double c0 = pr.y * inv, c1 = pr.z * inv, c2 = pr.w * inv;
        double t0 = tp[n], t1 = tp[MPTS + n], t2 = tp[2 * MPTS + n];
        Ssum[0] += s0; Ssum[1] += s1; Ssum[2] += s2;
        Csum[0] += c0; Csum[1] += c1; Csum[2] += c2;
        Tsum[0] += t0; Tsum[1] += t1; Tsum[2] += t2;
        P[0] += s0*c0; P[1] += s0*c1; P[2] += s0*c2;
        P[3] += s1*c0; P[4] += s1*c1; P[5] += s1*c2;
        P[6] += s2*c0; P[7] += s2*c1; P[8] += s2*c2;
    }
#pragma unroll
    for (int i = 0; i < 3; i++) {
        atomicAdd(&acc[i],     Ssum[i]);
        atomicAdd(&acc[3 + i], Csum[i]);
        atomicAdd(&acc[6 + i], Tsum[i]);
    }
#pragma unroll
    for (int i = 0; i < 9; i++) atomicAdd(&acc[9 + i], P[i]);
    __syncthreads();

    if (tid != 0) return;

    const double invN = 1.0 / (double)NPTS;
    double sm[3], cm[3], tm_[3];
    for (int i = 0; i < 3; i++) {
        sm[i]  = acc[i] * invN;
        cm[i]  = acc[3 + i] * invN;
        tm_[i] = acc[6 + i] * invN;
    }
    double H[3][3];
    for (int i = 0; i < 3; i++)
        for (int j = 0; j < 3; j++)
            H[i][j] = acc[9 + i * 3 + j] - (double)NPTS * sm[i] * cm[j];

    double A[3][3];
    for (int i = 0; i < 3; i++)
        for (int j = 0; j < 3; j++) {
            double s = 0.0;
            for (int k = 0; k < 3; k++) s += H[k][i] * H[k][j];
            A[i][j] = s;
        }

    double V[3][3] = {{1,0,0},{0,1,0},{0,0,1}};
    const int pp[3] = {0, 0, 1};
    const int qq[3] = {1, 2, 2};
    for (int it = 0; it < 30; it++) {
        const int p = pp[it % 3], q = qq[it % 3];
        const double apq = A[p][q];
        if (fabs(apq) < 1e-300) continue;
        const double theta = (A[q][q] - A[p][p]) / (2.0 * apq);
        const double t = (theta >= 0 ? 1.0 : -1.0) / (fabs(theta) + sqrt(theta * theta + 1.0));
        const double c = 1.0 / sqrt(t * t + 1.0);
        const double s = t * c;
        for (int k = 0; k < 3; k++) {
            const double akp = A[k][p], akq = A[k][q];
            A[k][p] = c * akp - s * akq;
            A[k][q] = s * akp + c * akq;
        }
        for (int k = 0; k < 3; k++) {
            const double apk = A[p][k], aqk = A[q][k];
            A[p][k] = c * apk - s * aqk;
            A[q][k] = s * apk + c * aqk;
        }
        for (int k = 0; k < 3; k++) {
            const double vkp = V[k][p], vkq = V[k][q];
            V[k][p] = c * vkp - s * vkq;
            V[k][q] = s * vkp + c * vkq;
        }
    }

    double lam[3] = {A[0][0], A[1][1], A[2][2]};
    int idx[3] = {0, 1, 2};
    for (int i = 0; i < 2; i++)
        for (int j = i + 1; j < 3; j++)
            if (lam[idx[j]] > lam[idx[i]]) { int tmpi = idx[i]; idx[i] = idx[j]; idx[j] = tmpi; }

    double v1[3], v2[3];
    for (int k = 0; k < 3; k++) { v1[k] = V[k][idx[0]]; v2[k] = V[k][idx[1]]; }

    double hv1[3], hv2[3];
    for (int i = 0; i < 3; i++) {
        hv1[i] = H[i][0]*v1[0] + H[i][1]*v1[1] + H[i][2]*v1[2];
        hv2[i] = H[i][0]*v2[0] + H[i][1]*v2[1] + H[i][2]*v2[2];
    }
    double n1 = sqrt(hv1[0]*hv1[0] + hv1[1]*hv1[1] + hv1[2]*hv1[2]);
    double u1[3] = {hv1[0]/n1, hv1[1]/n1, hv1[2]/n1};
    double d12 = u1[0]*hv2[0] + u1[1]*hv2[1] + u1[2]*hv2[2];
    double w[3] = {hv2[0] - d12*u1[0], hv2[1] - d12*u1[1], hv2[2] - d12*u1[2]};
    double n2 = sqrt(w[0]*w[0] + w[1]*w[1] + w[2]*w[2]);
    double u2[3] = {w[0]/n2, w[1]/n2, w[2]/n2};

    double v3[3] = {v1[1]*v2[2]-v1[2]*v2[1], v1[2]*v2[0]-v1[0]*v2[2], v1[0]*v2[1]-v1[1]*v2[0]};
    double u3[3] = {u1[1]*u2[2]-u1[2]*u2[1], u1[2]*u2[0]-u1[0]*u2[2], u1[0]*u2[1]-u1[1]*u2[0]};

    double R[3][3];
    for (int i = 0; i < 3; i++)
        for (int j = 0; j < 3; j++)
            R[i][j] = v1[i]*u1[j] + v2[i]*u2[j] + v3[i]*u3[j];

    double tvec[3];
    for (int i = 0; i < 3; i++)
        tvec[i] = -(R[i][0]*sm[0] + R[i][1]*sm[1] + R[i][2]*sm[2]) + tm_[i];

    for (int i = 0; i < 3; i++)
        for (int j = 0; j < 3; j++)
            out[b * 9 + i * 3 + j] = (float)R[i][j];
    for (int i = 0; i < 3; i++)
        out[BATCH * 9 + b * 3 + i] = (float)tvec[i];
}

// ---------------------------------------------------------------------------
extern "C" void kernel_launch(void* const* d_in, const int* in_sizes, int n_in,
                              void* d_out, int out_size) {
    const float* src_emb = (const float*)d_in[0];
    const float* tgt_emb = (const float*)d_in[1];
    const float* src     = (const float*)d_in[2];
    const float* tgt     = (const float*)d_in[3];
    float* out = (float*)d_out;

    cudaFuncSetAttribute(gemm_fused_kernel,
                         cudaFuncAttributeMaxDynamicSharedMemorySize, GEMM_SMEM);

    __half *ahi, *bhi, *blo;
    cudaGetSymbolAddress((void**)&ahi, g_Ahi);
    cudaGetSymbolAddress((void**)&bhi, g_Bhi);
    cudaGetSymbolAddress((void**)&blo, g_Blo);

    dim3 gc(NPTS / 32, DDIM / 32, BATCH);
    dim3 bc(32, 8);
    convA_kernel<<<gc, bc>>>(src_emb, ahi);
    convB_kernel<<<gc, bc>>>(tgt_emb, bhi, blo);

    zero_part_kernel<<<(BATCH * NPTS) / 256, 256>>>();

    dim3 g1(MPTS / BN, NPTS / BM, BATCH);   // (16, 8, 8)
    gemm_fused_kernel<<<g1, 512, GEMM_SMEM>>>(tgt);

    finalize_kernel<<<BATCH, 256>>>(src, tgt, out);
}

// round 5
// speedup vs baseline: 4.1443x; 1.8244x over previous
#include <cuda_runtime.h>
#include <cuda_fp16.h>
#include <cstdint>
#include <math.h>

#define BATCH 8
#define DDIM  512
#define NPTS  2048
#define MPTS  2048

// ---------------- scratch (__device__ globals: allowed) ----------------
__device__ float g_part[(size_t)BATCH * NPTS * 4];            // se, cx, cy, cz per (b,n)
__device__ __half g_Ahi[(size_t)BATCH * NPTS * DDIM];         // [B,N,D] K-major
__device__ __half g_Bhi[(size_t)BATCH * MPTS * DDIM];         // [B,M,D] K-major
__device__ __half g_Blo[(size_t)BATCH * MPTS * DDIM];

// ---------------- helpers ----------------
__device__ __forceinline__ uint32_t smem_u32(const void* p) {
    return (uint32_t)__cvta_generic_to_shared(p);
}
__device__ __forceinline__ void cpa16(uint32_t dst, const void* src) {
    asm volatile("cp.async.cg.shared.global [%0], [%1], 16;"
        :: "r"(dst), "l"(src) : "memory");
}
__device__ __forceinline__ void ldsm4(uint32_t* r, uint32_t addr) {
    asm volatile("ldmatrix.sync.aligned.m8n8.x4.shared.b16 {%0,%1,%2,%3}, [%4];"
        : "=r"(r[0]), "=r"(r[1]), "=r"(r[2]), "=r"(r[3]) : "r"(addr));
}
__device__ __forceinline__ void mma16816(float* c, const uint32_t* a, const uint32_t* b) {
    asm volatile(
        "mma.sync.aligned.m16n8k16.row.col.f32.f16.f16.f32 "
        "{%0,%1,%2,%3}, {%4,%5,%6,%7}, {%8,%9}, {%0,%1,%2,%3};"
        : "+f"(c[0]), "+f"(c[1]), "+f"(c[2]), "+f"(c[3])
        : "r"(a[0]), "r"(a[1]), "r"(a[2]), "r"(a[3]), "r"(b[0]), "r"(b[1]));
}

// ---------------------------------------------------------------------------
// Convert kernels: transpose [B][D][pts] -> [B][pts][D] fp16, 16B stores.
// Tile 64 d x 64 n.  SPLIT=true also emits the fp16 residual plane.
// ---------------------------------------------------------------------------
template<bool SPLIT>
__global__ __launch_bounds__(256)
void conv_kernel(const float* __restrict__ in,
                 __half* __restrict__ hi, __half* __restrict__ lo) {
    __shared__ float tile[64 * 65];
    const int b  = blockIdx.z;
    const int d0 = blockIdx.y * 64;
    const int n0 = blockIdx.x * 64;
    const int tid = threadIdx.x;

#pragma unroll
    for (int p = 0; p < 16; p++) {
        const int idx = tid + p * 256;
        const int dl = idx >> 6, nl = idx & 63;
        tile[dl * 65 + nl] = in[((size_t)b * DDIM + d0 + dl) * NPTS + n0 + nl];
    }
    __syncthreads();

    const int dg = tid & 7;          // 8-wide d group
#pragma unroll
    for (int pass = 0; pass < 2; pass++) {
        const int nl = (tid >> 3) + pass * 32;
        float v[8];
#pragma unroll
        for (int i = 0; i < 8; i++) v[i] = tile[(dg * 8 + i) * 65 + nl];

        __half h[8];
#pragma unroll
        for (int i = 0; i < 8; i++) h[i] = __float2half(v[i]);
        const size_t ofs = ((size_t)b * NPTS + n0 + nl) * DDIM + d0 + dg * 8;
        *(uint4*)&hi[ofs] = *(uint4*)h;

        if (SPLIT) {
            __half l[8];
#pragma unroll
            for (int i = 0; i < 8; i++) l[i] = __float2half(v[i] - __half2float(h[i]));
            *(uint4*)&lo[ofs] = *(uint4*)l;
        }
    }
}

// ---------------------------------------------------------------------------
// Kernel Z: zero the partial accumulators.
// ---------------------------------------------------------------------------
__global__ __launch_bounds__(256)
void zero_part_kernel() {
    const int i = blockIdx.x * 256 + threadIdx.x;
    ((float4*)g_part)[i] = make_float4(0.f, 0.f, 0.f, 0.f);
}

// ---------------------------------------------------------------------------
// Kernel 1: fused GEMM (fp16 2-term HMMA) + exp + weighted partial reduction.
// (unchanged from R4 — 185us @ tensor 61%)
// ---------------------------------------------------------------------------
#define BM 256
#define BN 128
#define BK 32
#define NCHUNK (DDIM / BK)       // 16

#define STAGE_BYTES 32768
#define OFF_AHI 0                 // 16384 bytes
#define OFF_BHI 16384             //  8192
#define OFF_BLO 24576             //  8192
#define SM_TGT  (4 * STAGE_BYTES)
#define GEMM_SMEM (SM_TGT + 1536)

__global__ __launch_bounds__(512, 1)
void gemm_fused_kernel(const float* __restrict__ tgt) {
    extern __shared__ char smem[];
    const uint32_t sb = smem_u32(smem);
    float* smem_tgt = (float*)(smem + SM_TGT);
    const int tid  = threadIdx.x;
    const int lane = tid & 31;
    const int wid  = tid >> 5;
    const int b  = blockIdx.z;
    const int n0 = blockIdx.y * BM;
    const int m0 = blockIdx.x * BN;
    const int warpN = wid & 7;
    const int warpM = wid >> 3;

    if (tid < 384) {
        const int dim = tid >> 7, col = tid & 127;
        smem_tgt[dim * 128 + col] = tgt[(size_t)b * 3 * MPTS + dim * MPTS + m0 + col];
    }

    const __half* Ah = g_Ahi + ((size_t)b * NPTS + n0) * DDIM;
    const __half* Bh = g_Bhi + ((size_t)b * MPTS + m0) * DDIM;
    const __half* Bl = g_Blo + ((size_t)b * MPTS + m0) * DDIM;

    const int ar0 = tid >> 2,         as0 = tid & 3;
    const int ar1 = (tid + 512) >> 2, as1 = (tid + 512) & 3;
    const int br  = tid >> 2,         bs  = tid & 3;
    const uint32_t ad0 = (uint32_t)(ar0 * 64 + ((as0 ^ ((ar0 >> 1) & 3)) * 16));
    const uint32_t ad1 = (uint32_t)(ar1 * 64 + ((as1 ^ ((ar1 >> 1) & 3)) * 16));
    const uint32_t bd  = (uint32_t)(br  * 64 + ((bs  ^ ((br  >> 1) & 3)) * 16));

    const int rowA = warpN * 32 + (lane & 15);
    const int khA  = lane >> 4;
    const int swzA = (rowA >> 1) & 3;
    const uint32_t abase = (uint32_t)(rowA * 64);
    const int rowB = warpM * 64 + (lane & 7) + ((lane >> 4) << 3);
    const int khB  = (lane >> 3) & 1;
    const int swzB = (rowB >> 1) & 3;
    const uint32_t bbase = (uint32_t)(rowB * 64);

    float acc[2][8][4];
#pragma unroll
    for (int i = 0; i < 2; i++)
#pragma unroll
        for (int j = 0; j < 8; j++)
#pragma unroll
            for (int k = 0; k < 4; k++) acc[i][j][k] = 0.f;

#pragma unroll 1
    for (int pc = 0; pc < 3; pc++) {
        const uint32_t st = sb + pc * STAGE_BYTES;
        const int kofs = pc * BK;
        cpa16(st + OFF_AHI + ad0, Ah + (size_t)ar0 * DDIM + kofs + as0 * 8);
        cpa16(st + OFF_AHI + ad1, Ah + (size_t)ar1 * DDIM + kofs + as1 * 8);
        cpa16(st + OFF_BHI + bd,  Bh + (size_t)br * DDIM + kofs + bs * 8);
        cpa16(st + OFF_BLO + bd,  Bl + (size_t)br * DDIM + kofs + bs * 8);
        asm volatile("cp.async.commit_group;" ::: "memory");
    }

#pragma unroll 1
    for (int kc = 0; kc < NCHUNK; kc++) {
        asm volatile("cp.async.wait_group 2;" ::: "memory");
        __syncthreads();
        const uint32_t st = sb + (kc & 3) * STAGE_BYTES;

#pragma unroll
        for (int kk = 0; kk < 2; kk++) {
            uint32_t ah[2][4];
            const uint32_t sa = (uint32_t)(((kk * 2 + khA) ^ swzA) * 16);
            ldsm4(ah[0], st + OFF_AHI + abase + sa);
            ldsm4(ah[1], st + OFF_AHI + abase + 1024 + sa);
            const uint32_t sg = (uint32_t)(((kk * 2 + khB) ^ swzB) * 16);
#pragma unroll
            for (int q = 0; q < 4; q++) {
                uint32_t bh[4], bl[4];
                ldsm4(bh, st + OFF_BHI + bbase + q * 1024 + sg);
                ldsm4(bl, st + OFF_BLO + bbase + q * 1024 + sg);
#pragma unroll
                for (int h = 0; h < 2; h++) {
                    const int j = q * 2 + h;
#pragma unroll
                    for (int i = 0; i < 2; i++) {
                        mma16816(acc[i][j], ah[i], bh + h * 2);
                        mma16816(acc[i][j], ah[i], bl + h * 2);
                    }
                }
            }
        }
        __syncthreads();

        const int nk = kc + 3;
        if (nk < NCHUNK) {
            const uint32_t st2 = sb + (nk & 3) * STAGE_BYTES;
            const int kofs = nk * BK;
            cpa16(st2 + OFF_AHI + ad0, Ah + (size_t)ar0 * DDIM + kofs + as0 * 8);
            cpa16(st2 + OFF_AHI + ad1, Ah + (size_t)ar1 * DDIM + kofs + as1 * 8);
            cpa16(st2 + OFF_BHI + bd,  Bh + (size_t)br * DDIM + kofs + bs * 8);
            cpa16(st2 + OFF_BLO + bd,  Bl + (size_t)br * DDIM + kofs + bs * 8);
        }
        asm volatile("cp.async.commit_group;" ::: "memory");
    }

    const float scale = 0.044194173824159216f;   // 1/sqrt(512)
    const int gr  = lane >> 2;
    const int tig = lane & 3;

#pragma unroll
    for (int i = 0; i < 2; i++) {
#pragma unroll
        for (int half = 0; half < 2; half++) {
            float se = 0.f, cx = 0.f, cy = 0.f, cz = 0.f;
#pragma unroll
            for (int j = 0; j < 8; j++) {
#pragma unroll
                for (int cc = 0; cc < 2; cc++) {
                    const float e = __expf(acc[i][j][half * 2 + cc] * scale);
                    const int col = warpM * 64 + j * 8 + tig * 2 + cc;
                    se += e;
                    cx += e * smem_tgt[col];
                    cy += e * smem_tgt[128 + col];
                    cz += e * smem_tgt[256 + col];
                }
            }
#pragma unroll
            for (int o = 1; o <= 2; o <<= 1) {
                se += __shfl_xor_sync(0xFFFFFFFFu, se, o);
                cx += __shfl_xor_sync(0xFFFFFFFFu, cx, o);
                cy += __shfl_xor_sync(0xFFFFFFFFu, cy, o);
                cz += __shfl_xor_sync(0xFFFFFFFFu, cz, o);
            }
            if (tig == 0) {
                const int n = n0 + warpN * 32 + i * 16 + half * 8 + gr;
                float* gp = g_part + ((size_t)b * NPTS + n) * 4;
                atomicAdd(gp + 0, se);
                atomicAdd(gp + 1, cx);
                atomicAdd(gp + 2, cy);
                atomicAdd(gp + 3, cz);
            }
        }
    }
}

// ---------------------------------------------------------------------------
// Kernel 3: per batch reductions + 3x3 Procrustes, fp32 throughout.
// ---------------------------------------------------------------------------
__global__ __launch_bounds__(256)
void finalize_kernel(const float* __restrict__ src, const float* __restrict__ tgt,
                     float* __restrict__ out) {
    const int b    = blockIdx.x;
    const int tid  = threadIdx.x;
    const int lane = tid & 31;

    const float* sp = src + (size_t)b * 3 * NPTS;
    const float4* pp4 = (const float4*)(g_part + (size_t)b * NPTS * 4);
    const float* tp = tgt + (size_t)b * 3 * MPTS;

    __shared__ float acc[18];
    if (tid < 18) acc[tid] = 0.0f;
    __syncthreads();

    float red[18];
#pragma unroll
    for (int i = 0; i < 18; i++) red[i] = 0.f;

    for (int n = tid; n < NPTS; n += 256) {
        const float s0 = sp[n], s1 = sp[NPTS + n], s2 = sp[2 * NPTS + n];
        const float4 pr = pp4[n];
        const float inv = __frcp_rn(pr.x);
        const float c0 = pr.y * inv, c1 = pr.z * inv, c2 = pr.w * inv;
        const float t0 = tp[n], t1 = tp[MPTS + n], t2 = tp[2 * MPTS + n];
        red[0] += s0; red[1] += s1; red[2] += s2;
        red[3] += c0; red[4] += c1; red[5] += c2;
        red[6] += t0; red[7] += t1; red[8] += t2;
        red[9]  += s0*c0; red[10] += s0*c1; red[11] += s0*c2;
        red[12] += s1*c0; red[13] += s1*c1; red[14] += s1*c2;
        red[15] += s2*c0; red[16] += s2*c1; red[17] += s2*c2;
    }
#pragma unroll
    for (int i = 0; i < 18; i++) {
#pragma unroll
        for (int o = 16; o; o >>= 1) red[i] += __shfl_xor_sync(0xFFFFFFFFu, red[i], o);
    }
    if (lane == 0) {
#pragma unroll
        for (int i = 0; i < 18; i++) atomicAdd(&acc[i], red[i]);
    }
    __syncthreads();

    if (tid != 0) return;

    const float invN = 1.0f / (float)NPTS;
    float sm[3], cm[3], tm_[3];
    for (int i = 0; i < 3; i++) {
        sm[i]  = acc[i] * invN;
        cm[i]  = acc[3 + i] * invN;
        tm_[i] = acc[6 + i] * invN;
    }
    float H[3][3];
    for (int i = 0; i < 3; i++)
        for (int j = 0; j < 3; j++)
            H[i][j] = acc[9 + i * 3 + j] - (float)NPTS * sm[i] * cm[j];

    float A[3][3];
    for (int i = 0; i < 3; i++)
        for (int j = 0; j < 3; j++) {
            float s = 0.0f;
            for (int k = 0; k < 3; k++) s += H[k][i] * H[k][j];
            A[i][j] = s;
        }

    float V[3][3] = {{1,0,0},{0,1,0},{0,0,1}};
    const int pp[3] = {0, 0, 1};
    const int qq[3] = {1, 2, 2};
#pragma unroll 1
    for (int it = 0; it < 24; it++) {
        const int p = pp[it % 3], q = qq[it % 3];
        const float apq = A[p][q];
        if (fabsf(apq) < 1e-30f) continue;
        const float theta = (A[q][q] - A[p][p]) / (2.0f * apq);
        const float t = (theta >= 0 ? 1.0f : -1.0f) / (fabsf(theta) + sqrtf(theta * theta + 1.0f));
        const float c = rsqrtf(t * t + 1.0f);
        const float s = t * c;
        for (int k = 0; k < 3; k++) {
            const float akp = A[k][p], akq = A[k][q];
            A[k][p] = c * akp - s * akq;
            A[k][q] = s * akp + c * akq;
        }
        for (int k = 0; k < 3; k++) {
            const float apk = A[p][k], aqk = A[q][k];
            A[p][k] = c * apk - s * aqk;
            A[q][k] = s * apk + c * aqk;
        }
        for (int k = 0; k < 3; k++) {
            const float vkp = V[k][p], vkq = V[k][q];
            V[k][p] = c * vkp - s * vkq;
            V[k][q] = s * vkp + c * vkq;
        }
    }

    float lam[3] = {A[0][0], A[1][1], A[2][2]};
    int idx[3] = {0, 1, 2};
    for (int i = 0; i < 2; i++)
        for (int j = i + 1; j < 3; j++)
            if (lam[idx[j]] > lam[idx[i]]) { int tmpi = idx[i]; idx[i] = idx[j]; idx[j] = tmpi; }

    float v1[3], v2[3];
    for (int k = 0; k < 3; k++) { v1[k] = V[k][idx[0]]; v2[k] = V[k][idx[1]]; }

    float hv1[3], hv2[3];
    for (int i = 0; i < 3; i++) {
        hv1[i] = H[i][0]*v1[0] + H[i][1]*v1[1] + H[i][2]*v1[2];
        hv2[i] = H[i][0]*v2[0] + H[i][1]*v2[1] + H[i][2]*v2[2];
    }
    const float in1 = rsqrtf(hv1[0]*hv1[0] + hv1[1]*hv1[1] + hv1[2]*hv1[2]);
    float u1[3] = {hv1[0]*in1, hv1[1]*in1, hv1[2]*in1};
    const float d12 = u1[0]*hv2[0] + u1[1]*hv2[1] + u1[2]*hv2[2];
    float w[3] = {hv2[0] - d12*u1[0], hv2[1] - d12*u1[1], hv2[2] - d12*u1[2]};
    const float in2 = rsqrtf(w[0]*w[0] + w[1]*w[1] + w[2]*w[2]);
    float u2[3] = {w[0]*in2, w[1]*in2, w[2]*in2};

    float v3[3] = {v1[1]*v2[2]-v1[2]*v2[1], v1[2]*v2[0]-v1[0]*v2[2], v1[0]*v2[1]-v1[1]*v2[0]};
    float u3[3] = {u1[1]*u2[2]-u1[2]*u2[1], u1[2]*u2[0]-u1[0]*u2[2], u1[0]*u2[1]-u1[1]*u2[0]};

    float R[3][3];
    for (int i = 0; i < 3; i++)
        for (int j = 0; j < 3; j++)
            R[i][j] = v1[i]*u1[j] + v2[i]*u2[j] + v3[i]*u3[j];

    float tvec[3];
    for (int i = 0; i < 3; i++)
        tvec[i] = -(R[i][0]*sm[0] + R[i][1]*sm[1] + R[i][2]*sm[2]) + tm_[i];

    for (int i = 0; i < 3; i++)
        for (int j = 0; j < 3; j++)
            out[b * 9 + i * 3 + j] = R[i][j];
    for (int i = 0; i < 3; i++)
        out[BATCH * 9 + b * 3 + i] = tvec[i];
}

// ---------------------------------------------------------------------------
extern "C" void kernel_launch(void* const* d_in, const int* in_sizes, int n_in,
                              void* d_out, int out_size) {
    const float* src_emb = (const float*)d_in[0];
    const float* tgt_emb = (const float*)d_in[1];
    const float* src     = (const float*)d_in[2];
    const float* tgt     = (const float*)d_in[3];
    float* out = (float*)d_out;

    cudaFuncSetAttribute(gemm_fused_kernel,
                         cudaFuncAttributeMaxDynamicSharedMemorySize, GEMM_SMEM);

    __half *ahi, *bhi, *blo;
    cudaGetSymbolAddress((void**)&ahi, g_Ahi);
    cudaGetSymbolAddress((void**)&bhi, g_Bhi);
    cudaGetSymbolAddress((void**)&blo, g_Blo);

    dim3 gc(NPTS / 64, DDIM / 64, BATCH);   // (32, 8, 8)
    conv_kernel<false><<<gc, 256>>>(src_emb, ahi, nullptr);
    conv_kernel<true ><<<gc, 256>>>(tgt_emb, bhi, blo);

    zero_part_kernel<<<(BATCH * NPTS) / 256, 256>>>();

    dim3 g1(MPTS / BN, NPTS / BM, BATCH);   // (16, 8, 8)
    gemm_fused_kernel<<<g1, 512, GEMM_SMEM>>>(tgt);

    finalize_kernel<<<BATCH, 256>>>(src, tgt, out);
}

// round 6
// speedup vs baseline: 4.5424x; 1.0961x over previous
#include <cuda_runtime.h>
#include <cuda_fp16.h>
#include <cstdint>
#include <math.h>

#define BATCH 8
#define DDIM  512
#define NPTS  2048
#define MPTS  2048

// ---------------- scratch (__device__ globals: allowed) ----------------
__device__ float g_part[(size_t)BATCH * NPTS * 4];            // se, cx, cy, cz per (b,n)
__device__ __half g_Ahi[(size_t)BATCH * NPTS * DDIM];         // [B,N,D] K-major
__device__ __half g_Bhi[(size_t)BATCH * MPTS * DDIM];         // [B,M,D] K-major
__device__ __half g_Blo[(size_t)BATCH * MPTS * DDIM];

// ---------------- helpers ----------------
__device__ __forceinline__ uint32_t smem_u32(const void* p) {
    return (uint32_t)__cvta_generic_to_shared(p);
}
__device__ __forceinline__ void cpa16(uint32_t dst, const void* src) {
    asm volatile("cp.async.cg.shared.global [%0], [%1], 16;"
        :: "r"(dst), "l"(src) : "memory");
}
__device__ __forceinline__ void ldsm4(uint32_t* r, uint32_t addr) {
    asm volatile("ldmatrix.sync.aligned.m8n8.x4.shared.b16 {%0,%1,%2,%3}, [%4];"
        : "=r"(r[0]), "=r"(r[1]), "=r"(r[2]), "=r"(r[3]) : "r"(addr));
}
__device__ __forceinline__ void mma16816(float* c, const uint32_t* a, const uint32_t* b) {
    asm volatile(
        "mma.sync.aligned.m16n8k16.row.col.f32.f16.f16.f32 "
        "{%0,%1,%2,%3}, {%4,%5,%6,%7}, {%8,%9}, {%0,%1,%2,%3};"
        : "+f"(c[0]), "+f"(c[1]), "+f"(c[2]), "+f"(c[3])
        : "r"(a[0]), "r"(a[1]), "r"(a[2]), "r"(a[3]), "r"(b[0]), "r"(b[1]));
}

// ---------------------------------------------------------------------------
// Convert kernels: transpose [B][D][pts] -> [B][pts][D] fp16, 16B stores.
// ---------------------------------------------------------------------------
template<bool SPLIT>
__global__ __launch_bounds__(256)
void conv_kernel(const float* __restrict__ in,
                 __half* __restrict__ hi, __half* __restrict__ lo) {
    __shared__ float tile[64 * 65];
    const int b  = blockIdx.z;
    const int d0 = blockIdx.y * 64;
    const int n0 = blockIdx.x * 64;
    const int tid = threadIdx.x;

#pragma unroll
    for (int p = 0; p < 16; p++) {
        const int idx = tid + p * 256;
        const int dl = idx >> 6, nl = idx & 63;
        tile[dl * 65 + nl] = in[((size_t)b * DDIM + d0 + dl) * NPTS + n0 + nl];
    }
    __syncthreads();

    const int dg = tid & 7;
#pragma unroll
    for (int pass = 0; pass < 2; pass++) {
        const int nl = (tid >> 3) + pass * 32;
        float v[8];
#pragma unroll
        for (int i = 0; i < 8; i++) v[i] = tile[(dg * 8 + i) * 65 + nl];

        __half h[8];
#pragma unroll
        for (int i = 0; i < 8; i++) h[i] = __float2half(v[i]);
        const size_t ofs = ((size_t)b * NPTS + n0 + nl) * DDIM + d0 + dg * 8;
        *(uint4*)&hi[ofs] = *(uint4*)h;

        if (SPLIT) {
            __half l[8];
#pragma unroll
            for (int i = 0; i < 8; i++) l[i] = __float2half(v[i] - __half2float(h[i]));
            *(uint4*)&lo[ofs] = *(uint4*)l;
        }
    }
}

// ---------------------------------------------------------------------------
// Kernel Z: zero the partial accumulators.
// ---------------------------------------------------------------------------
__global__ __launch_bounds__(256)
void zero_part_kernel() {
    const int i = blockIdx.x * 256 + threadIdx.x;
    ((float4*)g_part)[i] = make_float4(0.f, 0.f, 0.f, 0.f);
}

// ---------------------------------------------------------------------------
// Kernel 1: fused GEMM (fp16 2-term HMMA) + exp + weighted partial reduction.
// Tile 128(n) x 128(m), K-chunk 32, 256 threads / 8 warps, warp tile 32x64,
// 4-stage cp.async pipeline, 2 CTAs/SM for barrier-latency overlap.
// ---------------------------------------------------------------------------
#define BM 128
#define BN 128
#define BK 32
#define NCHUNK (DDIM / BK)       // 16

#define STAGE_BYTES 24576
#define OFF_AHI 0                 // 8192 bytes (128 rows x 64B)
#define OFF_BHI 8192              // 8192
#define OFF_BLO 16384             // 8192
#define SM_TGT  (4 * STAGE_BYTES) // 98304
#define GEMM_SMEM (SM_TGT + 1536)

__global__ __launch_bounds__(256, 2)
void gemm_fused_kernel(const float* __restrict__ tgt) {
    extern __shared__ char smem[];
    const uint32_t sb = smem_u32(smem);
    float* smem_tgt = (float*)(smem + SM_TGT);
    const int tid  = threadIdx.x;
    const int lane = tid & 31;
    const int wid  = tid >> 5;
    const int b  = blockIdx.z;
    const int n0 = blockIdx.y * BM;
    const int m0 = blockIdx.x * BN;
    const int warpN = wid & 3;     // 4 warps along n (4*32 = 128)
    const int warpM = wid >> 2;    // 2 warps along m (2*64 = 128)

    // stage 128-col tgt tile (3 dims)
    if (tid < 128) {
#pragma unroll
        for (int dim = 0; dim < 3; dim++)
            smem_tgt[dim * 128 + tid] =
                tgt[(size_t)b * 3 * MPTS + dim * MPTS + m0 + tid];
    }

    const __half* Ah = g_Ahi + ((size_t)b * NPTS + n0) * DDIM;
    const __half* Bh = g_Bhi + ((size_t)b * MPTS + m0) * DDIM;
    const __half* Bl = g_Blo + ((size_t)b * MPTS + m0) * DDIM;

    // loader mapping: each plane 512 segs, 2 per thread (idx = tid, tid+256)
    const int r0 = tid >> 2,         s0 = tid & 3;
    const int r1 = (tid + 256) >> 2, s1 = (tid + 256) & 3;
    const uint32_t d0 = (uint32_t)(r0 * 64 + ((s0 ^ ((r0 >> 1) & 3)) * 16));
    const uint32_t d1 = (uint32_t)(r1 * 64 + ((s1 ^ ((r1 >> 1) & 3)) * 16));

    // compute-side ldmatrix lane addressing
    const int rowA = warpN * 32 + (lane & 15);
    const int khA  = lane >> 4;
    const int swzA = (rowA >> 1) & 3;
    const uint32_t abase = (uint32_t)(rowA * 64);
    const int rowB = warpM * 64 + (lane & 7) + ((lane >> 4) << 3);
    const int khB  = (lane >> 3) & 1;
    const int swzB = (rowB >> 1) & 3;
    const uint32_t bbase = (uint32_t)(rowB * 64);

    float acc[2][8][4];
#pragma unroll
    for (int i = 0; i < 2; i++)
#pragma unroll
        for (int j = 0; j < 8; j++)
#pragma unroll
            for (int k = 0; k < 4; k++) acc[i][j][k] = 0.f;

    // preload 3 stages
#pragma unroll 1
    for (int pc = 0; pc < 3; pc++) {
        const uint32_t st = sb + pc * STAGE_BYTES;
        const int kofs = pc * BK;
        cpa16(st + OFF_AHI + d0, Ah + (size_t)r0 * DDIM + kofs + s0 * 8);
        cpa16(st + OFF_AHI + d1, Ah + (size_t)r1 * DDIM + kofs + s1 * 8);
        cpa16(st + OFF_BHI + d0, Bh + (size_t)r0 * DDIM + kofs + s0 * 8);
        cpa16(st + OFF_BHI + d1, Bh + (size_t)r1 * DDIM + kofs + s1 * 8);
        cpa16(st + OFF_BLO + d0, Bl + (size_t)r0 * DDIM + kofs + s0 * 8);
        cpa16(st + OFF_BLO + d1, Bl + (size_t)r1 * DDIM + kofs + s1 * 8);
        asm volatile("cp.async.commit_group;" ::: "memory");
    }

#pragma unroll 1
    for (int kc = 0; kc < NCHUNK; kc++) {
        asm volatile("cp.async.wait_group 2;" ::: "memory");
        __syncthreads();
        const uint32_t st = sb + (kc & 3) * STAGE_BYTES;

#pragma unroll
        for (int kk = 0; kk < 2; kk++) {
            uint32_t ah[2][4];
            const uint32_t sa = (uint32_t)(((kk * 2 + khA) ^ swzA) * 16);
            ldsm4(ah[0], st + OFF_AHI + abase + sa);
            ldsm4(ah[1], st + OFF_AHI + abase + 1024 + sa);
            const uint32_t sg = (uint32_t)(((kk * 2 + khB) ^ swzB) * 16);
#pragma unroll
            for (int q = 0; q < 4; q++) {
                uint32_t bh[4], bl[4];
                ldsm4(bh, st + OFF_BHI + bbase + q * 1024 + sg);
                ldsm4(bl, st + OFF_BLO + bbase + q * 1024 + sg);
#pragma unroll
                for (int h = 0; h < 2; h++) {
                    const int j = q * 2 + h;
#pragma unroll
                    for (int i = 0; i < 2; i++) {
                        mma16816(acc[i][j], ah[i], bh + h * 2);
                        mma16816(acc[i][j], ah[i], bl + h * 2);
                    }
                }
            }
        }
        __syncthreads();

        const int nk = kc + 3;
        if (nk < NCHUNK) {
            const uint32_t st2 = sb + (nk & 3) * STAGE_BYTES;
            const int kofs = nk * BK;
            cpa16(st2 + OFF_AHI + d0, Ah + (size_t)r0 * DDIM + kofs + s0 * 8);
            cpa16(st2 + OFF_AHI + d1, Ah + (size_t)r1 * DDIM + kofs + s1 * 8);
            cpa16(st2 + OFF_BHI + d0, Bh + (size_t)r0 * DDIM + kofs + s0 * 8);
            cpa16(st2 + OFF_BHI + d1, Bh + (size_t)r1 * DDIM + kofs + s1 * 8);
            cpa16(st2 + OFF_BLO + d0, Bl + (size_t)r0 * DDIM + kofs + s0 * 8);
            cpa16(st2 + OFF_BLO + d1, Bl + (size_t)r1 * DDIM + kofs + s1 * 8);
        }
        asm volatile("cp.async.commit_group;" ::: "memory");
    }

    // ---- fused epilogue: exp + weighted per-row partial reduction ----
    const float scale = 0.044194173824159216f;   // 1/sqrt(512)
    const int gr  = lane >> 2;
    const int tig = lane & 3;

#pragma unroll
    for (int i = 0; i < 2; i++) {
#pragma unroll
        for (int half = 0; half < 2; half++) {
            float se = 0.f, cx = 0.f, cy = 0.f, cz = 0.f;
#pragma unroll
            for (int j = 0; j < 8; j++) {
#pragma unroll
                for (int cc = 0; cc < 2; cc++) {
                    const float e = __expf(acc[i][j][half * 2 + cc] * scale);
                    const int col = warpM * 64 + j * 8 + tig * 2 + cc;
                    se += e;
                    cx += e * smem_tgt[col];
                    cy += e * smem_tgt[128 + col];
                    cz += e * smem_tgt[256 + col];
                }
            }
#pragma unroll
            for (int o = 1; o <= 2; o <<= 1) {
                se += __shfl_xor_sync(0xFFFFFFFFu, se, o);
                cx += __shfl_xor_sync(0xFFFFFFFFu, cx, o);
                cy += __shfl_xor_sync(0xFFFFFFFFu, cy, o);
                cz += __shfl_xor_sync(0xFFFFFFFFu, cz, o);
            }
            if (tig == 0) {
                const int n = n0 + warpN * 32 + i * 16 + half * 8 + gr;
                float* gp = g_part + ((size_t)b * NPTS + n) * 4;
                atomicAdd(gp + 0, se);
                atomicAdd(gp + 1, cx);
                atomicAdd(gp + 2, cy);
                atomicAdd(gp + 3, cz);
            }
        }
    }
}

// ---------------------------------------------------------------------------
// Kernel 3: per batch reductions + 3x3 Procrustes, fp32 throughout.
// ---------------------------------------------------------------------------
__global__ __launch_bounds__(256)
void finalize_kernel(const float* __restrict__ src, const float* __restrict__ tgt,
                     float* __restrict__ out) {
    const int b    = blockIdx.x;
    const int tid  = threadIdx.x;
    const int lane = tid & 31;

    const float* sp = src + (size_t)b * 3 * NPTS;
    const float4* pp4 = (const float4*)(g_part + (size_t)b * NPTS * 4);
    const float* tp = tgt + (size_t)b * 3 * MPTS;

    __shared__ float acc[18];
    if (tid < 18) acc[tid] = 0.0f;
    __syncthreads();

    float red[18];
#pragma unroll
    for (int i = 0; i < 18; i++) red[i] = 0.f;

    for (int n = tid; n < NPTS; n += 256) {
        const float s0 = sp[n], s1 = sp[NPTS + n], s2 = sp[2 * NPTS + n];
        const float4 pr = pp4[n];
        const float inv = __frcp_rn(pr.x);
        const float c0 = pr.y * inv, c1 = pr.z * inv, c2 = pr.w * inv;
        const float t0 = tp[n], t1 = tp[MPTS + n], t2 = tp[2 * MPTS + n];
        red[0] += s0; red[1] += s1; red[2] += s2;
        red[3] += c0; red[4] += c1; red[5] += c2;
        red[6] += t0; red[7] += t1; red[8] += t2;
        red[9]  += s0*c0; red[10] += s0*c1; red[11] += s0*c2;
        red[12] += s1*c0; red[13] += s1*c1; red[14] += s1*c2;
        red[15] += s2*c0; red[16] += s2*c1; red[17] += s2*c2;
    }
#pragma unroll
    for (int i = 0; i < 18; i++) {
#pragma unroll
        for (int o = 16; o; o >>= 1) red[i] += __shfl_xor_sync(0xFFFFFFFFu, red[i], o);
    }
    if (lane == 0) {
#pragma unroll
        for (int i = 0; i < 18; i++) atomicAdd(&acc[i], red[i]);
    }
    __syncthreads();

    if (tid != 0) return;

    const float invN = 1.0f / (float)NPTS;
    float sm[3], cm[3], tm_[3];
    for (int i = 0; i < 3; i++) {
        sm[i]  = acc[i] * invN;
        cm[i]  = acc[3 + i] * invN;
        tm_[i] = acc[6 + i] * invN;
    }
    float H[3][3];
    for (int i = 0; i < 3; i++)
        for (int j = 0; j < 3; j++)
            H[i][j] = acc[9 + i * 3 + j] - (float)NPTS * sm[i] * cm[j];

    float A[3][3];
    for (int i = 0; i < 3; i++)
        for (int j = 0; j < 3; j++) {
            float s = 0.0f;
            for (int k = 0; k < 3; k++) s += H[k][i] * H[k][j];
            A[i][j] = s;
        }

    float V[3][3] = {{1,0,0},{0,1,0},{0,0,1}};
    const int pp[3] = {0, 0, 1};
    const int qq[3] = {1, 2, 2};
#pragma unroll 1
    for (int it = 0; it < 24; it++) {
        const int p = pp[it % 3], q = qq[it % 3];
        const float apq = A[p][q];
        if (fabsf(apq) < 1e-30f) continue;
        const float theta = (A[q][q] - A[p][p]) / (2.0f * apq);
        const float t = (theta >= 0 ? 1.0f : -1.0f) / (fabsf(theta) + sqrtf(theta * theta + 1.0f));
        const float c = rsqrtf(t * t + 1.0f);
        const float s = t * c;
        for (int k = 0; k < 3; k++) {
            const float akp = A[k][p], akq = A[k][q];
            A[k][p] = c * akp - s * akq;
            A[k][q] = s * akp + c * akq;
        }
        for (int k = 0; k < 3; k++) {
            const float apk = A[p][k], aqk = A[q][k];
            A[p][k] = c * apk - s * aqk;
            A[q][k] = s * apk + c * aqk;
        }
        for (int k = 0; k < 3; k++) {
            const float vkp = V[k][p], vkq = V[k][q];
            V[k][p] = c * vkp - s * vkq;
            V[k][q] = s * vkp + c * vkq;
        }
    }

    float lam[3] = {A[0][0], A[1][1], A[2][2]};
    int idx[3] = {0, 1, 2};
    for (int i = 0; i < 2; i++)
        for (int j = i + 1; j < 3; j++)
            if (lam[idx[j]] > lam[idx[i]]) { int tmpi = idx[i]; idx[i] = idx[j]; idx[j] = tmpi; }

    float v1[3], v2[3];
    for (int k = 0; k < 3; k++) { v1[k] = V[k][idx[0]]; v2[k] = V[k][idx[1]]; }

    float hv1[3], hv2[3];
    for (int i = 0; i < 3; i++) {
        hv1[i] = H[i][0]*v1[0] + H[i][1]*v1[1] + H[i][2]*v1[2];
        hv2[i] = H[i][0]*v2[0] + H[i][1]*v2[1] + H[i][2]*v2[2];
    }
    const float in1 = rsqrtf(hv1[0]*hv1[0] + hv1[1]*hv1[1] + hv1[2]*hv1[2]);
    float u1[3] = {hv1[0]*in1, hv1[1]*in1, hv1[2]*in1};
    const float d12 = u1[0]*hv2[0] + u1[1]*hv2[1] + u1[2]*hv2[2];
    float w[3] = {hv2[0] - d12*u1[0], hv2[1] - d12*u1[1], hv2[2] - d12*u1[2]};
    const float in2 = rsqrtf(w[0]*w[0] + w[1]*w[1] + w[2]*w[2]);
    float u2[3] = {w[0]*in2, w[1]*in2, w[2]*in2};

    float v3[3] = {v1[1]*v2[2]-v1[2]*v2[1], v1[2]*v2[0]-v1[0]*v2[2], v1[0]*v2[1]-v1[1]*v2[0]};
    float u3[3] = {u1[1]*u2[2]-u1[2]*u2[1], u1[2]*u2[0]-u1[0]*u2[2], u1[0]*u2[1]-u1[1]*u2[0]};

    float R[3][3];
    for (int i = 0; i < 3; i++)
        for (int j = 0; j < 3; j++)
            R[i][j] = v1[i]*u1[j] + v2[i]*u2[j] + v3[i]*u3[j];

    float tvec[3];
    for (int i = 0; i < 3; i++)
        tvec[i] = -(R[i][0]*sm[0] + R[i][1]*sm[1] + R[i][2]*sm[2]) + tm_[i];

    for (int i = 0; i < 3; i++)
        for (int j = 0; j < 3; j++)
            out[b * 9 + i * 3 + j] = R[i][j];
    for (int i = 0; i < 3; i++)
        out[BATCH * 9 + b * 3 + i] = tvec[i];
}

// ---------------------------------------------------------------------------
extern "C" void kernel_launch(void* const* d_in, const int* in_sizes, int n_in,
                              void* d_out, int out_size) {
    const float* src_emb = (const float*)d_in[0];
    const float* tgt_emb = (const float*)d_in[1];
    const float* src     = (const float*)d_in[2];
    const float* tgt     = (const float*)d_in[3];
    float* out = (float*)d_out;

    cudaFuncSetAttribute(gemm_fused_kernel,
                         cudaFuncAttributeMaxDynamicSharedMemorySize, GEMM_SMEM);

    __half *ahi, *bhi, *blo;
    cudaGetSymbolAddress((void**)&ahi, g_Ahi);
    cudaGetSymbolAddress((void**)&bhi, g_Bhi);
    cudaGetSymbolAddress((void**)&blo, g_Blo);

    dim3 gc(NPTS / 64, DDIM / 64, BATCH);   // (32, 8, 8)
    conv_kernel<false><<<gc, 256>>>(src_emb, ahi, nullptr);
    conv_kernel<true ><<<gc, 256>>>(tgt_emb, bhi, blo);

    zero_part_kernel<<<(BATCH * NPTS) / 256, 256>>>();

    dim3 g1(MPTS / BN, NPTS / BM, BATCH);   // (16, 16, 8)
    gemm_fused_kernel<<<g1, 256, GEMM_SMEM>>>(tgt);

    finalize_kernel<<<BATCH, 256>>>(src, tgt, out);
}